// round 14
// baseline (speedup 1.0000x reference)
#include <cuda_runtime.h>
#include <math.h>

#define Bx 256
#define Sx 196
#define Rx 2048
#define Ax 512
#define NSPLIT 16
#define KCHUNK (Rx / NSPLIT)  // 128
#define SCHUNK 49             // rows per score block (4 blocks per batch)

// Scratch (allocation-free rule: __device__ globals)
__device__ float g_part[NSPLIT * Bx * Ax];   // 8 MB split-K partials
__device__ float g_scores[Bx * Sx];          // 200 KB raw scores

// Second stream + events, created once at static-init.
static cudaStream_t g_s2;
static cudaEvent_t g_ev1, g_ev2;
static struct StreamInit {
    StreamInit() {
        cudaStreamCreate(&g_s2);
        cudaEventCreateWithFlags(&g_ev1, cudaEventDisableTiming);
        cudaEventCreateWithFlags(&g_ev2, cudaEventDisableTiming);
    }
} g_stream_init;

// Fast tanh: MUFU.EX2 + MUFU.RCP + FMA. ~1e-7 rel err.
__device__ __forceinline__ float fast_tanh(float x) {
    float ax = fabsf(x);
    float e = __expf(2.0f * ax);
    float r;
    asm("rcp.approx.f32 %0, %1;" : "=f"(r) : "f"(e + 1.0f));
    r = fmaf(-2.0f, r, 1.0f);
    return copysignf(r, x);
}

// ---------------------------------------------------------------------------
// K0: stream p_att (103 MB, fits in 126 MB L2) into L2.
// TINY grid (64x128): occupies ~2% of warp slots so the concurrent gemm keeps
// its SMs; prefetches are fire-and-forget, DRAM queue drains in background.
// ---------------------------------------------------------------------------
__global__ __launch_bounds__(128)
void k_prefetch(const float* __restrict__ p) {
    const size_t NLINES = (size_t)Bx * Sx * Ax * 4 / 128;  // 802816
    size_t stride = (size_t)gridDim.x * blockDim.x;        // 8192
    const char* c = reinterpret_cast<const char*>(p);
    for (size_t i = (size_t)blockIdx.x * blockDim.x + threadIdx.x; i < NLINES; i += stride)
        asm volatile("prefetch.global.L2 [%0];" :: "l"(c + i * 128));
}

// ---------------------------------------------------------------------------
// K1: att_h partials = h[B,R] @ W_h[R,A], split-K over z.
// BM=128 BN=64 BK=16, 256 threads, 8x4 tile, double-buffered smem,
// one barrier per K-step. (verified 20.1us standalone)
// ---------------------------------------------------------------------------
__global__ __launch_bounds__(256)
void k_gemm(const float* __restrict__ h, const float* __restrict__ Wh) {
    const int BM = 128, BN = 64, BK = 16;
    __shared__ float As[2][BK][BM + 4];
    __shared__ float Bs[2][BK][BN];

    int tid = threadIdx.x;
    int tx = tid & 15;
    int ty = tid >> 4;
    int bm = blockIdx.y * BM;
    int bn = blockIdx.x * BN;
    int kc0 = blockIdx.z * KCHUNK;

    float acc[8][4];
#pragma unroll
    for (int i = 0; i < 8; i++)
#pragma unroll
        for (int j = 0; j < 4; j++) acc[i][j] = 0.f;

    float pa[8], pb[4];
#pragma unroll
    for (int j = 0; j < 8; j++) {
        int lin = tid + 256 * j;
        pa[j] = h[(size_t)(bm + (lin >> 4)) * Rx + kc0 + (lin & 15)];
    }
#pragma unroll
    for (int j = 0; j < 4; j++) {
        int lin = tid + 256 * j;
        pb[j] = Wh[(size_t)(kc0 + (lin >> 6)) * Ax + bn + (lin & 63)];
    }

    const int NT = KCHUNK / BK;  // 8
#pragma unroll
    for (int t = 0; t < NT; t++) {
        int cur = t & 1;
#pragma unroll
        for (int j = 0; j < 8; j++) {
            int lin = tid + 256 * j;
            As[cur][lin & 15][lin >> 4] = pa[j];
        }
#pragma unroll
        for (int j = 0; j < 4; j++) {
            int lin = tid + 256 * j;
            Bs[cur][lin >> 6][lin & 63] = pb[j];
        }
        __syncthreads();

        if (t < NT - 1) {
            int kc = kc0 + (t + 1) * BK;
#pragma unroll
            for (int j = 0; j < 8; j++) {
                int lin = tid + 256 * j;
                pa[j] = h[(size_t)(bm + (lin >> 4)) * Rx + kc + (lin & 15)];
            }
#pragma unroll
            for (int j = 0; j < 4; j++) {
                int lin = tid + 256 * j;
                pb[j] = Wh[(size_t)(kc + (lin >> 6)) * Ax + bn + (lin & 63)];
            }
        }

#pragma unroll
        for (int kk = 0; kk < BK; kk++) {
            float4 a0 = *reinterpret_cast<const float4*>(&As[cur][kk][ty * 8]);
            float4 a1 = *reinterpret_cast<const float4*>(&As[cur][kk][ty * 8 + 4]);
            float4 b4 = *reinterpret_cast<const float4*>(&Bs[cur][kk][tx * 4]);
            float av[8] = {a0.x, a0.y, a0.z, a0.w, a1.x, a1.y, a1.z, a1.w};
            float bv[4] = {b4.x, b4.y, b4.z, b4.w};
#pragma unroll
            for (int i = 0; i < 8; i++)
#pragma unroll
                for (int j = 0; j < 4; j++)
                    acc[i][j] += av[i] * bv[j];
        }
    }

    float* out = g_part + (size_t)blockIdx.z * Bx * Ax;
#pragma unroll
    for (int i = 0; i < 8; i++) {
        int m = bm + ty * 8 + i;
        float4 v = make_float4(acc[i][0], acc[i][1], acc[i][2], acc[i][3]);
        *reinterpret_cast<float4*>(&out[(size_t)m * Ax + bn + tx * 4]) = v;
    }
}

// ---------------------------------------------------------------------------
// K2: raw scores. grid (4, B): block q handles 49 rows of batch b.
// att_h reduced inline from split-K partials (+ b_h). p_att L2-resident.
// ---------------------------------------------------------------------------
__global__ __launch_bounds__(256)
void k_scores_raw(const float* __restrict__ p_att,
                  const float* __restrict__ W_a,
                  const float* __restrict__ b_a,
                  const float* __restrict__ b_h) {
    int b = blockIdx.y;
    int q = blockIdx.x;
    __shared__ float sh_ah[Ax];
    __shared__ float sh_wa[Ax];

    int tid = threadIdx.x;
#pragma unroll
    for (int e = 0; e < 2; e++) {
        int a = tid + 256 * e;
        float v = b_h[a];
#pragma unroll
        for (int z = 0; z < NSPLIT; z++)
            v += g_part[(size_t)z * Bx * Ax + (size_t)b * Ax + a];
        sh_ah[a] = v;
        sh_wa[a] = W_a[a];
    }
    __syncthreads();

    int warp = tid >> 5, lane = tid & 31;
    float ba = b_a[0];
    int s_end = (q + 1) * SCHUNK;
    if (s_end > Sx) s_end = Sx;

    for (int s = q * SCHUNK + warp; s < s_end; s += 8) {
        const float4* p = reinterpret_cast<const float4*>(p_att + ((size_t)b * Sx + s) * Ax);
        float acc = 0.f;
#pragma unroll
        for (int i = 0; i < 4; i++) {
            float4 v  = p[lane + 32 * i];
            float4 ah = reinterpret_cast<const float4*>(sh_ah)[lane + 32 * i];
            float4 wa = reinterpret_cast<const float4*>(sh_wa)[lane + 32 * i];
            acc += fast_tanh(v.x + ah.x) * wa.x;
            acc += fast_tanh(v.y + ah.y) * wa.y;
            acc += fast_tanh(v.z + ah.z) * wa.z;
            acc += fast_tanh(v.w + ah.w) * wa.w;
        }
#pragma unroll
        for (int o = 16; o > 0; o >>= 1) acc += __shfl_xor_sync(0xffffffffu, acc, o);
        if (lane == 0) g_scores[(size_t)b * Sx + s] = acc + ba;
    }
}

// ---------------------------------------------------------------------------
// K3: softmax (redundant per block, L2-resident) + weighted sum.
// grid (4, B), 128 threads. HBM streaming with __ldcs + unroll 8.
// ---------------------------------------------------------------------------
__global__ __launch_bounds__(128)
void k_wsum(const float* __restrict__ att_feats,
            const unsigned char* __restrict__ mask,
            float* __restrict__ out) {
    int b = blockIdx.y;
    int tid = threadIdx.x;  // 0..127
    __shared__ float sw[Sx];
    __shared__ float red[8];
    int warp = tid >> 5, lane = tid & 31;

    float v0 = g_scores[(size_t)b * Sx + tid];
    if (mask[(size_t)b * Sx + tid]) v0 = -100000000.0f;
    float v1 = -INFINITY;
    if (tid < Sx - 128) {
        v1 = g_scores[(size_t)b * Sx + tid + 128];
        if (mask[(size_t)b * Sx + tid + 128]) v1 = -100000000.0f;
    }
    float m = fmaxf(v0, v1);
#pragma unroll
    for (int o = 16; o > 0; o >>= 1) m = fmaxf(m, __shfl_xor_sync(0xffffffffu, m, o));
    if (lane == 0) red[warp] = m;
    __syncthreads();
    float smax = fmaxf(fmaxf(red[0], red[1]), fmaxf(red[2], red[3]));

    float e0 = __expf(v0 - smax);
    float e1 = (tid < Sx - 128) ? __expf(v1 - smax) : 0.f;
    float ssum = e0 + e1;
#pragma unroll
    for (int o = 16; o > 0; o >>= 1) ssum += __shfl_xor_sync(0xffffffffu, ssum, o);
    if (lane == 0) red[warp + 4] = ssum;
    __syncthreads();
    float inv = 1.0f / (red[4] + red[5] + red[6] + red[7]);
    sw[tid] = e0 * inv;
    if (tid < Sx - 128) sw[tid + 128] = e1 * inv;
    __syncthreads();

    const float4* base = reinterpret_cast<const float4*>(att_feats + (size_t)b * Sx * Rx)
                         + blockIdx.x * 128 + tid;
    float4 acc = make_float4(0.f, 0.f, 0.f, 0.f);
#pragma unroll 2
    for (int s0 = 0; s0 < 192; s0 += 8) {
        float4 v[8];
#pragma unroll
        for (int u = 0; u < 8; u++)
            v[u] = __ldcs(&base[(size_t)(s0 + u) * (Rx / 4)]);
#pragma unroll
        for (int u = 0; u < 8; u++) {
            float w = sw[s0 + u];
            acc.x += w * v[u].x;
            acc.y += w * v[u].y;
            acc.z += w * v[u].z;
            acc.w += w * v[u].w;
        }
    }
#pragma unroll
    for (int s = 192; s < Sx; s++) {
        float w = sw[s];
        float4 v = __ldcs(&base[(size_t)s * (Rx / 4)]);
        acc.x += w * v.x;
        acc.y += w * v.y;
        acc.z += w * v.z;
        acc.w += w * v.w;
    }
    reinterpret_cast<float4*>(out + (size_t)b * Rx)[blockIdx.x * 128 + tid] = acc;
}

// ---------------------------------------------------------------------------
extern "C" void kernel_launch(void* const* d_in, const int* in_sizes, int n_in,
                              void* d_out, int out_size) {
    const float*         h         = (const float*)d_in[0];
    const float*         att_feats = (const float*)d_in[1];
    const float*         p_att     = (const float*)d_in[2];
    const unsigned char* mask      = (const unsigned char*)d_in[3];
    const float*         W_h       = (const float*)d_in[4];
    const float*         b_h       = (const float*)d_in[5];
    const float*         W_a       = (const float*)d_in[6];
    const float*         b_a       = (const float*)d_in[7];
    float*               out       = (float*)d_out;

    // Fork: tiny-grid prefetch of p_att into L2 on g_s2, concurrent with
    // k_gemm (which uses ~4% DRAM). Join before k_scores_raw.
    cudaEventRecord(g_ev1, 0);
    cudaStreamWaitEvent(g_s2, g_ev1, 0);
    k_prefetch<<<64, 128, 0, g_s2>>>(p_att);
    cudaEventRecord(g_ev2, g_s2);

    k_gemm<<<dim3(Ax / 64, Bx / 128, NSPLIT), 256>>>(h, W_h);

    cudaStreamWaitEvent(0, g_ev2, 0);
    k_scores_raw<<<dim3(4, Bx), 256>>>(p_att, W_a, b_a, b_h);
    k_wsum<<<dim3(4, Bx), 128>>>(att_feats, mask, out);
}

// round 17
// speedup vs baseline: 1.1902x; 1.1902x over previous
#include <cuda_runtime.h>
#include <math.h>

#define Bx 256
#define Sx 196
#define Rx 2048
#define Ax 512
#define NSPLIT 16
#define KCHUNK (Rx / NSPLIT)  // 128
#define SCHUNK 49             // rows per score block (4 blocks per batch)

// Scratch (allocation-free rule: __device__ globals)
__device__ float g_part[NSPLIT * Bx * Ax];   // 8 MB split-K partials
__device__ float g_scores[Bx * Sx];          // 200 KB raw scores

// Fast tanh: MUFU.EX2 + MUFU.RCP + FMA. ~1e-7 rel err.
__device__ __forceinline__ float fast_tanh(float x) {
    float ax = fabsf(x);
    float e = __expf(2.0f * ax);
    float r;
    asm("rcp.approx.f32 %0, %1;" : "=f"(r) : "f"(e + 1.0f));
    r = fmaf(-2.0f, r, 1.0f);
    return copysignf(r, x);
}

// Packed f32x2 helpers (FFMA2: 2 fp32 FMA lanes per instruction)
__device__ __forceinline__ unsigned long long pk2(float lo, float hi) {
    unsigned long long r;
    asm("mov.b64 %0, {%1, %2};" : "=l"(r) : "f"(lo), "f"(hi));
    return r;
}
__device__ __forceinline__ void upk2(unsigned long long v, float& lo, float& hi) {
    asm("mov.b64 {%0, %1}, %2;" : "=f"(lo), "=f"(hi) : "l"(v));
}
__device__ __forceinline__ void ffma2(unsigned long long& d,
                                      unsigned long long a, unsigned long long b) {
    asm("fma.rn.f32x2 %0, %1, %2, %0;" : "+l"(d) : "l"(a), "l"(b));
}

// ---------------------------------------------------------------------------
// K1: att_h partials = h[B,R] @ W_h[R,A], split-K over z.
// BM=128 BN=64 BK=16, 256 threads, 8x4 per-thread tile computed as 4x4
// packed f32x2 accumulators (M-row pairs). Double-buffered smem, one
// barrier per K-step.
// ---------------------------------------------------------------------------
__global__ __launch_bounds__(256)
void k_gemm(const float* __restrict__ h, const float* __restrict__ Wh) {
    const int BM = 128, BN = 64, BK = 16;
    __shared__ float As[2][BK][BM + 4];
    __shared__ float Bs[2][BK][BN];

    int tid = threadIdx.x;
    int tx = tid & 15;
    int ty = tid >> 4;
    int bm = blockIdx.y * BM;
    int bn = blockIdx.x * BN;
    int kc0 = blockIdx.z * KCHUNK;

    // acc2[p][j]: packed (row 2p, row 2p+1) x col j
    unsigned long long acc2[4][4];
#pragma unroll
    for (int p = 0; p < 4; p++)
#pragma unroll
        for (int j = 0; j < 4; j++) acc2[p][j] = 0ull;  // (0.f, 0.f)

    float pa[8], pb[4];
#pragma unroll
    for (int j = 0; j < 8; j++) {
        int lin = tid + 256 * j;
        pa[j] = h[(size_t)(bm + (lin >> 4)) * Rx + kc0 + (lin & 15)];
    }
#pragma unroll
    for (int j = 0; j < 4; j++) {
        int lin = tid + 256 * j;
        pb[j] = Wh[(size_t)(kc0 + (lin >> 6)) * Ax + bn + (lin & 63)];
    }

    const int NT = KCHUNK / BK;  // 8
#pragma unroll
    for (int t = 0; t < NT; t++) {
        int cur = t & 1;
#pragma unroll
        for (int j = 0; j < 8; j++) {
            int lin = tid + 256 * j;
            As[cur][lin & 15][lin >> 4] = pa[j];
        }
#pragma unroll
        for (int j = 0; j < 4; j++) {
            int lin = tid + 256 * j;
            Bs[cur][lin >> 6][lin & 63] = pb[j];
        }
        __syncthreads();

        if (t < NT - 1) {
            int kc = kc0 + (t + 1) * BK;
#pragma unroll
            for (int j = 0; j < 8; j++) {
                int lin = tid + 256 * j;
                pa[j] = h[(size_t)(bm + (lin >> 4)) * Rx + kc + (lin & 15)];
            }
#pragma unroll
            for (int j = 0; j < 4; j++) {
                int lin = tid + 256 * j;
                pb[j] = Wh[(size_t)(kc + (lin >> 6)) * Ax + bn + (lin & 63)];
            }
        }

#pragma unroll
        for (int kk = 0; kk < BK; kk++) {
            float4 a0 = *reinterpret_cast<const float4*>(&As[cur][kk][ty * 8]);
            float4 a1 = *reinterpret_cast<const float4*>(&As[cur][kk][ty * 8 + 4]);
            float4 b4 = *reinterpret_cast<const float4*>(&Bs[cur][kk][tx * 4]);
            unsigned long long ap[4] = {
                pk2(a0.x, a0.y), pk2(a0.z, a0.w),
                pk2(a1.x, a1.y), pk2(a1.z, a1.w)
            };
            unsigned long long bb[4] = {
                pk2(b4.x, b4.x), pk2(b4.y, b4.y),
                pk2(b4.z, b4.z), pk2(b4.w, b4.w)
            };
#pragma unroll
            for (int p = 0; p < 4; p++)
#pragma unroll
                for (int j = 0; j < 4; j++)
                    ffma2(acc2[p][j], ap[p], bb[j]);
        }
    }

    float* out = g_part + (size_t)blockIdx.z * Bx * Ax;
#pragma unroll
    for (int p = 0; p < 4; p++) {
        float lo[4], hi[4];
#pragma unroll
        for (int j = 0; j < 4; j++) upk2(acc2[p][j], lo[j], hi[j]);
        int m0 = bm + ty * 8 + 2 * p;
        *reinterpret_cast<float4*>(&out[(size_t)m0 * Ax + bn + tx * 4]) =
            make_float4(lo[0], lo[1], lo[2], lo[3]);
        *reinterpret_cast<float4*>(&out[(size_t)(m0 + 1) * Ax + bn + tx * 4]) =
            make_float4(hi[0], hi[1], hi[2], hi[3]);
    }
}

// ---------------------------------------------------------------------------
// K2: raw scores. grid (4, B): block q handles 49 rows of batch b.
// att_h reduced inline from split-K partials (+ b_h).
// ---------------------------------------------------------------------------
__global__ __launch_bounds__(256)
void k_scores_raw(const float* __restrict__ p_att,
                  const float* __restrict__ W_a,
                  const float* __restrict__ b_a,
                  const float* __restrict__ b_h) {
    int b = blockIdx.y;
    int q = blockIdx.x;
    __shared__ float sh_ah[Ax];
    __shared__ float sh_wa[Ax];

    int tid = threadIdx.x;
#pragma unroll
    for (int e = 0; e < 2; e++) {
        int a = tid + 256 * e;
        float v = b_h[a];
#pragma unroll
        for (int z = 0; z < NSPLIT; z++)
            v += g_part[(size_t)z * Bx * Ax + (size_t)b * Ax + a];
        sh_ah[a] = v;
        sh_wa[a] = W_a[a];
    }
    __syncthreads();

    int warp = tid >> 5, lane = tid & 31;
    float ba = b_a[0];
    int s_end = (q + 1) * SCHUNK;
    if (s_end > Sx) s_end = Sx;

    for (int s = q * SCHUNK + warp; s < s_end; s += 8) {
        const float4* p = reinterpret_cast<const float4*>(p_att + ((size_t)b * Sx + s) * Ax);
        float acc = 0.f;
#pragma unroll
        for (int i = 0; i < 4; i++) {
            float4 v  = __ldcs(&p[lane + 32 * i]);
            float4 ah = reinterpret_cast<const float4*>(sh_ah)[lane + 32 * i];
            float4 wa = reinterpret_cast<const float4*>(sh_wa)[lane + 32 * i];
            acc += fast_tanh(v.x + ah.x) * wa.x;
            acc += fast_tanh(v.y + ah.y) * wa.y;
            acc += fast_tanh(v.z + ah.z) * wa.z;
            acc += fast_tanh(v.w + ah.w) * wa.w;
        }
#pragma unroll
        for (int o = 16; o > 0; o >>= 1) acc += __shfl_xor_sync(0xffffffffu, acc, o);
        if (lane == 0) g_scores[(size_t)b * Sx + s] = acc + ba;
    }
}

// ---------------------------------------------------------------------------
// K3: softmax (redundant per block, L2-resident) + weighted sum.
// grid (4, B), 128 threads. HBM streaming with __ldcs + unroll 8.
// ---------------------------------------------------------------------------
__global__ __launch_bounds__(128)
void k_wsum(const float* __restrict__ att_feats,
            const unsigned char* __restrict__ mask,
            float* __restrict__ out) {
    int b = blockIdx.y;
    int tid = threadIdx.x;  // 0..127
    __shared__ float sw[Sx];
    __shared__ float red[8];
    int warp = tid >> 5, lane = tid & 31;

    float v0 = g_scores[(size_t)b * Sx + tid];
    if (mask[(size_t)b * Sx + tid]) v0 = -100000000.0f;
    float v1 = -INFINITY;
    if (tid < Sx - 128) {
        v1 = g_scores[(size_t)b * Sx + tid + 128];
        if (mask[(size_t)b * Sx + tid + 128]) v1 = -100000000.0f;
    }
    float m = fmaxf(v0, v1);
#pragma unroll
    for (int o = 16; o > 0; o >>= 1) m = fmaxf(m, __shfl_xor_sync(0xffffffffu, m, o));
    if (lane == 0) red[warp] = m;
    __syncthreads();
    float smax = fmaxf(fmaxf(red[0], red[1]), fmaxf(red[2], red[3]));

    float e0 = __expf(v0 - smax);
    float e1 = (tid < Sx - 128) ? __expf(v1 - smax) : 0.f;
    float ssum = e0 + e1;
#pragma unroll
    for (int o = 16; o > 0; o >>= 1) ssum += __shfl_xor_sync(0xffffffffu, ssum, o);
    if (lane == 0) red[warp + 4] = ssum;
    __syncthreads();
    float inv = 1.0f / (red[4] + red[5] + red[6] + red[7]);
    sw[tid] = e0 * inv;
    if (tid < Sx - 128) sw[tid + 128] = e1 * inv;
    __syncthreads();

    const float4* base = reinterpret_cast<const float4*>(att_feats + (size_t)b * Sx * Rx)
                         + blockIdx.x * 128 + tid;
    float4 acc = make_float4(0.f, 0.f, 0.f, 0.f);
#pragma unroll 2
    for (int s0 = 0; s0 < 192; s0 += 8) {
        float4 v[8];
#pragma unroll
        for (int u = 0; u < 8; u++)
            v[u] = __ldcs(&base[(size_t)(s0 + u) * (Rx / 4)]);
#pragma unroll
        for (int u = 0; u < 8; u++) {
            float w = sw[s0 + u];
            acc.x += w * v[u].x;
            acc.y += w * v[u].y;
            acc.z += w * v[u].z;
            acc.w += w * v[u].w;
        }
    }
#pragma unroll
    for (int s = 192; s < Sx; s++) {
        float w = sw[s];
        float4 v = __ldcs(&base[(size_t)s * (Rx / 4)]);
        acc.x += w * v.x;
        acc.y += w * v.y;
        acc.z += w * v.z;
        acc.w += w * v.w;
    }
    reinterpret_cast<float4*>(out + (size_t)b * Rx)[blockIdx.x * 128 + tid] = acc;
}

// ---------------------------------------------------------------------------
extern "C" void kernel_launch(void* const* d_in, const int* in_sizes, int n_in,
                              void* d_out, int out_size) {
    const float*         h         = (const float*)d_in[0];
    const float*         att_feats = (const float*)d_in[1];
    const float*         p_att     = (const float*)d_in[2];
    const unsigned char* mask      = (const unsigned char*)d_in[3];
    const float*         W_h       = (const float*)d_in[4];
    const float*         b_h       = (const float*)d_in[5];
    const float*         W_a       = (const float*)d_in[6];
    const float*         b_a       = (const float*)d_in[7];
    float*               out       = (float*)d_out;

    k_gemm<<<dim3(Ax / 64, Bx / 128, NSPLIT), 256>>>(h, W_h);
    k_scores_raw<<<dim3(4, Bx), 256>>>(p_att, W_a, b_a, b_h);
    k_wsum<<<dim3(4, Bx), 128>>>(att_feats, mask, out);
}